// round 16
// baseline (speedup 1.0000x reference)
#include <cuda_runtime.h>
#include <math.h>

#define BATCH 16
#define NC    2048
#define NT    2048
#define TG    2048
#define NBINS 128
#define RFAC  3.75f    // truncation tail ~ erfc(3.75/sqrt2) = 1.8e-4 << 1e-3 gate
#define EPS   1e-8f
#define LOG2E 1.4426950408889634f

typedef unsigned long long u64;

__device__ __forceinline__ float ex2(float x) {
    float y;
    asm("ex2.approx.ftz.f32 %0, %1;" : "=f"(y) : "f"(x));
    return y;
}

// packed f32x2 helpers (FFMA2 path — ptxas never auto-emits this)
__device__ __forceinline__ u64 dup_f32(float x) {
    u64 r; asm("mov.b64 %0, {%1, %1};" : "=l"(r) : "f"(x)); return r;
}
__device__ __forceinline__ void fma2(u64& acc, u64 a, u64 b) {
    asm("fma.rn.f32x2 %0, %1, %2, %0;" : "+l"(acc) : "l"(a), "l"(b));
}
__device__ __forceinline__ float2 unpk(u64 v) {
    float lo, hi; asm("mov.b64 {%0, %1}, %2;" : "=f"(lo), "=f"(hi) : "l"(v));
    return make_float2(lo, hi);
}

__device__ __forceinline__ int bin_fix(float x) {
    int b = (int)floorf(x);
    return min(NBINS - 1, max(0, b));
}

// ---------------- scratch (no allocs allowed) ----------------
__device__ float    g_minmax[2];
__device__ float    g_plo[BATCH], g_phi[BATCH];
__device__ unsigned g_done = 0;
__device__ int      g_starts[BATCH * (NBINS + 1)];
__device__ __align__(16) float2 g_sxy[BATCH * NC];
__device__ __align__(16) float2 g_f[BATCH * TG];

// ---------------- K1: fused hist + scan + scatter + minmax ----------------
#define SNTH 512
#define SPT  4   // NC / SNTH
__global__ __launch_bounds__(SNTH) void sort_kernel(
    const float* __restrict__ xc, const float* __restrict__ yc,
    const float* __restrict__ xt) {
    __shared__ int scnt[NBINS];
    __shared__ int scur[NBINS];
    __shared__ int wsum[16];
    __shared__ float slo[16], shi[16];
    int b = blockIdx.x, tid = threadIdx.x;
    int lane = tid & 31, w = tid >> 5;

    for (int i = tid; i < NBINS; i += SNTH) scnt[i] = 0;
    __syncthreads();

    const float* xcb = xc + b * NC;
    const float* ycb = yc + b * NC;
    const float* xtb = xt + b * NT;
    float xv[SPT], yv[SPT];
    float lo = INFINITY, hi = -INFINITY;
    #pragma unroll
    for (int r = 0; r < SPT; r++) {
        int i = tid + r * SNTH;
        xv[r] = __ldg(&xcb[i]);
        yv[r] = __ldg(&ycb[i]);
    }
    #pragma unroll
    for (int r = 0; r < SPT; r++) {
        lo = fminf(lo, xv[r]); hi = fmaxf(hi, xv[r]);
        atomicAdd(&scnt[bin_fix(xv[r])], 1);
    }
    #pragma unroll
    for (int r = 0; r < SPT; r++) {
        float v = __ldg(&xtb[tid + r * SNTH]);
        lo = fminf(lo, v); hi = fmaxf(hi, v);
    }
    #pragma unroll
    for (int off = 16; off; off >>= 1) {
        lo = fminf(lo, __shfl_xor_sync(0xffffffffu, lo, off));
        hi = fmaxf(hi, __shfl_xor_sync(0xffffffffu, hi, off));
    }
    if (lane == 0) { slo[w] = lo; shi[w] = hi; }
    __syncthreads();

    int c = (tid < NBINS) ? scnt[tid] : 0;
    int v = c;
    #pragma unroll
    for (int off = 1; off < 32; off <<= 1) {
        int n = __shfl_up_sync(0xffffffffu, v, off);
        if (lane >= off) v += n;
    }
    if (lane == 31) wsum[w] = v;
    __syncthreads();
    if (tid == 0) {
        int run = 0;
        #pragma unroll
        for (int k = 0; k < 16; k++) { int t = wsum[k]; wsum[k] = run; run += t; }
        float flo = slo[0], fhi = shi[0];
        #pragma unroll
        for (int k = 1; k < 16; k++) { flo = fminf(flo, slo[k]); fhi = fmaxf(fhi, shi[k]); }
        g_plo[b] = flo; g_phi[b] = fhi;
    }
    __syncthreads();
    if (tid < NBINS) {
        int excl = v - c + wsum[w];
        scur[tid] = excl;
        g_starts[b * (NBINS + 1) + tid] = excl;
    }
    if (tid == 0) g_starts[b * (NBINS + 1) + NBINS] = NC;
    __syncthreads();

    #pragma unroll
    for (int r = 0; r < SPT; r++) {
        int pos = atomicAdd(&scur[bin_fix(xv[r])], 1);
        g_sxy[b * NC + pos] = make_float2(xv[r], yv[r]);
    }

    __threadfence();
    if (tid == 0) {
        if (atomicAdd(&g_done, 1) == BATCH - 1) {
            __threadfence();
            volatile float* plo = g_plo;
            volatile float* phi = g_phi;
            float flo = INFINITY, fhi = -INFINITY;
            #pragma unroll
            for (int k = 0; k < BATCH; k++) {
                flo = fminf(flo, plo[k]); fhi = fmaxf(fhi, phi[k]);
            }
            g_minmax[0] = flo; g_minmax[1] = fhi;
            g_done = 0;
            __threadfence();
        }
    }
}

// ---------------- K2: fused psi + 4-layer conv chain ----------------
#define T_TILE 128
#define HALO   8
#define CW     (T_TILE + 2 * HALO)  // 144
#define CWP    152
#define CNTH   256

#define OFF_S0  0
#define OFF_S1  (OFF_S0 + 3 * CWP)
#define OFF_S2  (OFF_S1 + 16 * CWP)
#define OFF_W1  (OFF_S2 + 32 * CWP)
#define OFF_W2  (OFF_W1 + 240)
#define OFF_W3  (OFF_W2 + 2560)
#define OFF_W4  (OFF_W3 + 2560)
#define OFF_B1  (OFF_W4 + 160)
#define OFF_B2  (OFF_B1 + 16)
#define OFF_B3  (OFF_B2 + 32)
#define OFF_B4  (OFF_B3 + 16)
#define SMEM_FLOATS (OFF_B4 + 4)
#define SMEM_BYTES  (SMEM_FLOATS * 4)

// Inner loop uses packed f32x2 FMA: weight float4 halves are the (co q, co q+1)
// multiplier pairs (free via double2 reinterpret); inputs broadcast-packed once
// per ci. 40 FFMA2 replace 80 FFMA per (task, ci).
template <int NCO, int NCI, int LO>
__device__ __forceinline__ void conv_layer(const float* __restrict__ sin,
                                           float* __restrict__ sout,
                                           const float4* __restrict__ sw4,
                                           const float* __restrict__ sb,
                                           int p0, int tid) {
    constexpr int nv = CW - 2 * LO;
    constexpr int ngp = nv / 4;
    constexpr int ncog = NCO / 4;
    constexpr int off = (LO - 2) & 3;

    for (int task = tid; task < ncog * ngp; task += CNTH) {
        int gp = task % ngp;
        int cog = task / ngp;
        int u0 = LO + gp * 4;
        int base = u0 - 2 - off;

        u64 acc2[2][4];
        #pragma unroll
        for (int qp = 0; qp < 2; qp++)
            #pragma unroll
            for (int j = 0; j < 4; j++) acc2[qp][j] = 0ULL;

        for (int ci = 0; ci < NCI; ci++) {
            const float4* sr = reinterpret_cast<const float4*>(sin + ci * CWP + base);
            float4 A = sr[0], B = sr[1], C = sr[2];
            float win[12] = {A.x, A.y, A.z, A.w, B.x, B.y, B.z, B.w,
                             C.x, C.y, C.z, C.w};
            u64 wd[8];
            #pragma unroll
            for (int i = 0; i < 8; i++) wd[i] = dup_f32(win[off + i]);

            const double2* wrow = reinterpret_cast<const double2*>(
                sw4 + (cog * NCI + ci) * 5);
            #pragma unroll
            for (int k = 0; k < 5; k++) {
                double2 wq = wrow[k];
                u64 w01 = __double_as_longlong(wq.x);
                u64 w23 = __double_as_longlong(wq.y);
                #pragma unroll
                for (int j = 0; j < 4; j++) {
                    fma2(acc2[0][j], w01, wd[k + j]);
                    fma2(acc2[1][j], w23, wd[k + j]);
                }
            }
        }

        float acc[4][4];
        #pragma unroll
        for (int qp = 0; qp < 2; qp++)
            #pragma unroll
            for (int j = 0; j < 4; j++) {
                float2 p = unpk(acc2[qp][j]);
                acc[2 * qp][j] = p.x;
                acc[2 * qp + 1][j] = p.y;
            }

        #pragma unroll
        for (int q = 0; q < 4; q++) {
            int co = cog * 4 + q;
            float bias = sb[co];
            float v[4];
            #pragma unroll
            for (int j = 0; j < 4; j++) {
                int p = p0 + u0 + j;
                v[j] = (p >= 0 && p < TG) ? fmaxf(acc[q][j] + bias, 0.f) : 0.f;
            }
            float2* so = reinterpret_cast<float2*>(sout + co * CWP + u0);
            so[0] = make_float2(v[0], v[1]);
            so[1] = make_float2(v[2], v[3]);
        }
    }
}

__global__ __launch_bounds__(CNTH) void cnp_kernel(
    const float* __restrict__ pls, const float* __restrict__ pos_,
    const float* __restrict__ w1, const float* __restrict__ b1,
    const float* __restrict__ w2, const float* __restrict__ b2,
    const float* __restrict__ w3, const float* __restrict__ b3,
    const float* __restrict__ w4, const float* __restrict__ b4) {
    extern __shared__ float dsm[];
    float* s0 = dsm + OFF_S0;
    float* s1 = dsm + OFF_S1;
    float* s2 = dsm + OFF_S2;

    const int tiles = TG / T_TILE;
    int b = blockIdx.x / tiles;
    int tile = blockIdx.x % tiles;
    int p0 = tile * T_TILE - HALO;
    int tid = threadIdx.x;

    for (int i = tid; i < 240; i += CNTH) {
        int co = i / 15, r = i % 15;
        dsm[OFF_W1 + (co >> 2) * 60 + r * 4 + (co & 3)] = __ldg(&w1[i]);
    }
    for (int i = tid; i < 2560; i += CNTH) {
        int co = i / 80, r = i % 80;
        dsm[OFF_W2 + (co >> 2) * 320 + r * 4 + (co & 3)] = __ldg(&w2[i]);
    }
    for (int i = tid; i < 2560; i += CNTH) {
        int co = i / 160, r = i % 160;
        dsm[OFF_W3 + (co >> 2) * 640 + r * 4 + (co & 3)] = __ldg(&w3[i]);
    }
    for (int i = tid; i < 160; i += CNTH)  dsm[OFF_W4 + i] = __ldg(&w4[i]);
    if (tid < 16) dsm[OFF_B1 + tid] = __ldg(&b1[tid]);
    if (tid < 32) dsm[OFF_B2 + tid] = __ldg(&b2[tid]);
    if (tid >= 32 && tid < 48) dsm[OFF_B3 + tid - 32] = __ldg(&b3[tid - 32]);
    if (tid >= 48 && tid < 50) dsm[OFF_B4 + tid - 48] = __ldg(&b4[tid - 48]);

    float lower = g_minmax[0], upper = g_minmax[1];
    float dt = (upper - lower) / (float)(TG - 1);

    // ---- psi phase into s0: 4 sub-lanes per position ----
    {
        float ls = __ldg(pls), osv = __ldg(pos_);
        float nc2 = -0.5f * LOG2E / (ls * ls);
        float R = fabsf(ls) * RFAC;
        const int nb = b * (NBINS + 1);
        const float4* sp4 = reinterpret_cast<const float4*>(g_sxy + b * NC);

        for (int task = tid; task < CW * 4; task += CNTH) {
            int u = task >> 2, sub = task & 3;
            int p = p0 + u;
            bool in = (p >= 0 && p < TG);
            float t = lower + p * dt;
            float a00 = 0.f, a10 = 0.f, a01 = 0.f, a11 = 0.f;
            if (in) {
                int blo = min(NBINS - 1, max(0, (int)floorf(t - R)));
                int bhi = min(NBINS - 1, max(0, (int)floorf(t + R)));
                int s = g_starts[nb + blo];
                int e = g_starts[nb + bhi + 1];
                int j0 = (s >> 1) + sub;
                int j1 = (e - 1) >> 1;
                for (int j = j0; j <= j1; j += 4) {
                    float4 pt = __ldg(&sp4[j]);
                    float d0 = t - pt.x;
                    float d1 = t - pt.z;
                    float e0 = ex2(d0 * d0 * nc2);
                    float e1 = ex2(d1 * d1 * nc2);
                    a00 += e0; a10 = fmaf(e0, pt.y, a10);
                    a01 += e1; a11 = fmaf(e1, pt.w, a11);
                }
            }
            float a0 = a00 + a01, a1 = a10 + a11;
            #pragma unroll
            for (int off = 2; off; off >>= 1) {
                a0 += __shfl_xor_sync(0xffffffffu, a0, off);
                a1 += __shfl_xor_sync(0xffffffffu, a1, off);
            }
            if (sub == 0) {
                a0 *= osv; a1 *= osv;
                s0[0 * CWP + u] = in ? t : 0.f;
                s0[1 * CWP + u] = a0;
                s0[2 * CWP + u] = in ? a1 / (a0 + EPS) : 0.f;
            }
        }
    }
    __syncthreads();

    conv_layer<16, 3, 2>(s0, s1, reinterpret_cast<const float4*>(dsm + OFF_W1),
                         dsm + OFF_B1, p0, tid);
    __syncthreads();
    conv_layer<32, 16, 4>(s1, s2, reinterpret_cast<const float4*>(dsm + OFF_W2),
                          dsm + OFF_B2, p0, tid);
    __syncthreads();
    conv_layer<16, 32, 6>(s2, s1, reinterpret_cast<const float4*>(dsm + OFF_W3),
                          dsm + OFF_B3, p0, tid);
    __syncthreads();

    if (tid < T_TILE) {
        const float* sw4 = dsm + OFF_W4;
        const float* sb4 = dsm + OFF_B4;
        int u = HALO + tid;
        float acc0 = sb4[0], acc1 = sb4[1];
        #pragma unroll
        for (int ci = 0; ci < 16; ci++) {
            #pragma unroll
            for (int k = 0; k < 5; k++) {
                float xv = s1[ci * CWP + u - 2 + k];
                acc0 = fmaf(sw4[(0 * 16 + ci) * 5 + k], xv, acc0);
                acc1 = fmaf(sw4[(1 * 16 + ci) * 5 + k], xv, acc1);
            }
        }
        int p = p0 + u;
        float sp = fmaxf(acc1, 0.f) + log1pf(__expf(-fabsf(acc1)));
        g_f[b * TG + p] = make_float2(acc0, sp);
    }
}

// ---------------- K3: rho stage — 8 lanes per target, float4 loads ----------------
__global__ void rho_kernel(const float* __restrict__ xt,
                           const float* __restrict__ pls,
                           const float* __restrict__ pos_,
                           float* __restrict__ out) {
    int g = (blockIdx.x * blockDim.x + threadIdx.x) >> 3;
    int sub = threadIdx.x & 7;
    if (g >= BATCH * NT) return;
    int b = g >> 11;

    float lower = g_minmax[0];
    float dt = (g_minmax[1] - lower) / (float)(TG - 1);
    float inv_dt = 1.f / dt;
    float x = __ldg(&xt[g]);
    float ls = __ldg(pls), osv = __ldg(pos_);
    float nc2 = -0.5f * LOG2E / (ls * ls);
    float R = fabsf(ls) * RFAC;

    int ilo = max(0, (int)ceilf((x - R - lower) * inv_dt));
    int ihi = min(TG - 1, (int)floorf((x + R - lower) * inv_dt));

    int j0 = (ilo >> 1) + sub;
    int j1 = ihi >> 1;
    const float4* f4 = reinterpret_cast<const float4*>(g_f + b * TG);
    float mu0 = 0.f, sg0 = 0.f, mu1 = 0.f, sg1 = 0.f;
    float d0 = x - (lower + (float)(2 * j0) * dt);
    float step16 = 16.f * dt;
    for (int j = j0; j <= j1; j += 8) {
        float4 v = __ldg(&f4[j]);
        float d1 = d0 - dt;
        float e0 = ex2(d0 * d0 * nc2);
        float e1 = ex2(d1 * d1 * nc2);
        mu0 = fmaf(e0, v.x, mu0); sg0 = fmaf(e0, v.y, sg0);
        mu1 = fmaf(e1, v.z, mu1); sg1 = fmaf(e1, v.w, sg1);
        d0 -= step16;
    }
    float mu = mu0 + mu1, sg = sg0 + sg1;
    #pragma unroll
    for (int off = 4; off; off >>= 1) {
        mu += __shfl_xor_sync(0xffffffffu, mu, off);
        sg += __shfl_xor_sync(0xffffffffu, sg, off);
    }
    if (sub == 0) {
        reinterpret_cast<float2*>(out)[g] = make_float2(mu * osv, sg * osv);
    }
}

// ---------------- launch ----------------
extern "C" void kernel_launch(void* const* d_in, const int* in_sizes, int n_in,
                              void* d_out, int out_size) {
    const float* xc = (const float*)d_in[0];
    const float* yc = (const float*)d_in[1];
    const float* xt = (const float*)d_in[2];
    const float* ls_psi = (const float*)d_in[3];
    const float* os_psi = (const float*)d_in[4];
    const float* ls_rho = (const float*)d_in[5];
    const float* os_rho = (const float*)d_in[6];
    const float* w1 = (const float*)d_in[7];
    const float* b1 = (const float*)d_in[8];
    const float* w2 = (const float*)d_in[9];
    const float* b2 = (const float*)d_in[10];
    const float* w3 = (const float*)d_in[11];
    const float* b3 = (const float*)d_in[12];
    const float* w4 = (const float*)d_in[13];
    const float* b4 = (const float*)d_in[14];
    float* out = (float*)d_out;

    cudaFuncSetAttribute(cnp_kernel,
                         cudaFuncAttributeMaxDynamicSharedMemorySize, SMEM_BYTES);

    sort_kernel<<<BATCH, SNTH>>>(xc, yc, xt);
    cnp_kernel<<<BATCH * (TG / T_TILE), CNTH, SMEM_BYTES>>>(
        ls_psi, os_psi, w1, b1, w2, b2, w3, b3, w4, b4);
    rho_kernel<<<(BATCH * NT) * 8 / 256, 256>>>(xt, ls_rho, os_rho, out);
}

// round 17
// speedup vs baseline: 1.3973x; 1.3973x over previous
#include <cuda_runtime.h>
#include <math.h>

#define BATCH 16
#define NC    2048
#define NT    2048
#define TG    2048
#define NBINS 128
#define RFAC  3.75f    // truncation tail ~ erfc(3.75/sqrt2) = 1.8e-4 << 1e-3 gate
#define EPS   1e-8f
#define LOG2E 1.4426950408889634f

__device__ __forceinline__ float ex2(float x) {
    float y;
    asm("ex2.approx.ftz.f32 %0, %1;" : "=f"(y) : "f"(x));
    return y;
}

__device__ __forceinline__ int bin_fix(float x) {
    int b = (int)floorf(x);
    return min(NBINS - 1, max(0, b));
}

// ---------------- scratch (no allocs allowed) ----------------
__device__ float    g_minmax[2];
__device__ float    g_plo[BATCH], g_phi[BATCH];
__device__ unsigned g_done = 0;
__device__ int      g_starts[BATCH * (NBINS + 1)];
__device__ __align__(16) float2 g_sxy[BATCH * NC];
__device__ __align__(16) float2 g_f[BATCH * TG];

// ---------------- K1: fused hist + scan + scatter + minmax ----------------
#define SNTH 512
#define SPT  4   // NC / SNTH
__global__ __launch_bounds__(SNTH) void sort_kernel(
    const float* __restrict__ xc, const float* __restrict__ yc,
    const float* __restrict__ xt) {
    __shared__ int scnt[NBINS];
    __shared__ int scur[NBINS];
    __shared__ int wsum[16];
    __shared__ float slo[16], shi[16];
    int b = blockIdx.x, tid = threadIdx.x;
    int lane = tid & 31, w = tid >> 5;

    for (int i = tid; i < NBINS; i += SNTH) scnt[i] = 0;
    __syncthreads();

    const float* xcb = xc + b * NC;
    const float* ycb = yc + b * NC;
    const float* xtb = xt + b * NT;
    float xv[SPT], yv[SPT];
    float lo = INFINITY, hi = -INFINITY;
    #pragma unroll
    for (int r = 0; r < SPT; r++) {
        int i = tid + r * SNTH;
        xv[r] = __ldg(&xcb[i]);
        yv[r] = __ldg(&ycb[i]);
    }
    #pragma unroll
    for (int r = 0; r < SPT; r++) {
        lo = fminf(lo, xv[r]); hi = fmaxf(hi, xv[r]);
        atomicAdd(&scnt[bin_fix(xv[r])], 1);
    }
    #pragma unroll
    for (int r = 0; r < SPT; r++) {
        float v = __ldg(&xtb[tid + r * SNTH]);
        lo = fminf(lo, v); hi = fmaxf(hi, v);
    }
    #pragma unroll
    for (int off = 16; off; off >>= 1) {
        lo = fminf(lo, __shfl_xor_sync(0xffffffffu, lo, off));
        hi = fmaxf(hi, __shfl_xor_sync(0xffffffffu, hi, off));
    }
    if (lane == 0) { slo[w] = lo; shi[w] = hi; }
    __syncthreads();

    int c = (tid < NBINS) ? scnt[tid] : 0;
    int v = c;
    #pragma unroll
    for (int off = 1; off < 32; off <<= 1) {
        int n = __shfl_up_sync(0xffffffffu, v, off);
        if (lane >= off) v += n;
    }
    if (lane == 31) wsum[w] = v;
    __syncthreads();
    if (tid == 0) {
        int run = 0;
        #pragma unroll
        for (int k = 0; k < 16; k++) { int t = wsum[k]; wsum[k] = run; run += t; }
        float flo = slo[0], fhi = shi[0];
        #pragma unroll
        for (int k = 1; k < 16; k++) { flo = fminf(flo, slo[k]); fhi = fmaxf(fhi, shi[k]); }
        g_plo[b] = flo; g_phi[b] = fhi;
    }
    __syncthreads();
    if (tid < NBINS) {
        int excl = v - c + wsum[w];
        scur[tid] = excl;
        g_starts[b * (NBINS + 1) + tid] = excl;
    }
    if (tid == 0) g_starts[b * (NBINS + 1) + NBINS] = NC;
    __syncthreads();

    #pragma unroll
    for (int r = 0; r < SPT; r++) {
        int pos = atomicAdd(&scur[bin_fix(xv[r])], 1);
        g_sxy[b * NC + pos] = make_float2(xv[r], yv[r]);
    }

    __threadfence();
    if (tid == 0) {
        if (atomicAdd(&g_done, 1) == BATCH - 1) {
            __threadfence();
            volatile float* plo = g_plo;
            volatile float* phi = g_phi;
            float flo = INFINITY, fhi = -INFINITY;
            #pragma unroll
            for (int k = 0; k < BATCH; k++) {
                flo = fminf(flo, plo[k]); fhi = fmaxf(fhi, phi[k]);
            }
            g_minmax[0] = flo; g_minmax[1] = fhi;
            g_done = 0;
            __threadfence();
        }
    }
}

// ---------------- K2: fused psi (smem-staged) + 4-layer conv chain ----------------
#define T_TILE 128
#define HALO   8
#define CW     (T_TILE + 2 * HALO)  // 144
#define CWP    152
#define CNTH   256

#define OFF_S0  0
#define OFF_S1  (OFF_S0 + 3 * CWP)
#define OFF_S2  (OFF_S1 + 16 * CWP)    // s2: 4864 floats = 2432 float2 >= NC
#define OFF_W1  (OFF_S2 + 32 * CWP)
#define OFF_W2  (OFF_W1 + 240)
#define OFF_W3  (OFF_W2 + 2560)
#define OFF_W4  (OFF_W3 + 2560)
#define OFF_B1  (OFF_W4 + 160)
#define OFF_B2  (OFF_B1 + 16)
#define OFF_B3  (OFF_B2 + 32)
#define OFF_B4  (OFF_B3 + 16)
#define SMEM_FLOATS (OFF_B4 + 4)
#define SMEM_BYTES  (SMEM_FLOATS * 4)

template <int NCO, int NCI, int LO>
__device__ __forceinline__ void conv_layer(const float* __restrict__ sin,
                                           float* __restrict__ sout,
                                           const float4* __restrict__ sw4,
                                           const float* __restrict__ sb,
                                           int p0, int tid) {
    constexpr int nv = CW - 2 * LO;
    constexpr int ngp = nv / 4;
    constexpr int ncog = NCO / 4;
    constexpr int off = (LO - 2) & 3;

    for (int task = tid; task < ncog * ngp; task += CNTH) {
        int gp = task % ngp;
        int cog = task / ngp;
        int u0 = LO + gp * 4;
        int base = u0 - 2 - off;

        float acc[4][4];
        #pragma unroll
        for (int q = 0; q < 4; q++)
            #pragma unroll
            for (int j = 0; j < 4; j++) acc[q][j] = 0.f;

        for (int ci = 0; ci < NCI; ci++) {
            const float4* sr = reinterpret_cast<const float4*>(sin + ci * CWP + base);
            float4 A = sr[0], B = sr[1], C = sr[2];
            float win[12] = {A.x, A.y, A.z, A.w, B.x, B.y, B.z, B.w,
                             C.x, C.y, C.z, C.w};
            #pragma unroll
            for (int k = 0; k < 5; k++) {
                float4 wv = sw4[(cog * NCI + ci) * 5 + k];
                #pragma unroll
                for (int j = 0; j < 4; j++) {
                    float xv = win[off + k + j];
                    acc[0][j] = fmaf(wv.x, xv, acc[0][j]);
                    acc[1][j] = fmaf(wv.y, xv, acc[1][j]);
                    acc[2][j] = fmaf(wv.z, xv, acc[2][j]);
                    acc[3][j] = fmaf(wv.w, xv, acc[3][j]);
                }
            }
        }
        #pragma unroll
        for (int q = 0; q < 4; q++) {
            int co = cog * 4 + q;
            float bias = sb[co];
            float v[4];
            #pragma unroll
            for (int j = 0; j < 4; j++) {
                int p = p0 + u0 + j;
                v[j] = (p >= 0 && p < TG) ? fmaxf(acc[q][j] + bias, 0.f) : 0.f;
            }
            float2* so = reinterpret_cast<float2*>(sout + co * CWP + u0);
            so[0] = make_float2(v[0], v[1]);
            so[1] = make_float2(v[2], v[3]);
        }
    }
}

__global__ __launch_bounds__(CNTH) void cnp_kernel(
    const float* __restrict__ pls, const float* __restrict__ pos_,
    const float* __restrict__ w1, const float* __restrict__ b1,
    const float* __restrict__ w2, const float* __restrict__ b2,
    const float* __restrict__ w3, const float* __restrict__ b3,
    const float* __restrict__ w4, const float* __restrict__ b4) {
    extern __shared__ float dsm[];
    float* s0 = dsm + OFF_S0;
    float* s1 = dsm + OFF_S1;
    float* s2 = dsm + OFF_S2;

    const int tiles = TG / T_TILE;
    int b = blockIdx.x / tiles;
    int tile = blockIdx.x % tiles;
    int p0 = tile * T_TILE - HALO;
    int tid = threadIdx.x;

    for (int i = tid; i < 240; i += CNTH) {
        int co = i / 15, r = i % 15;
        dsm[OFF_W1 + (co >> 2) * 60 + r * 4 + (co & 3)] = __ldg(&w1[i]);
    }
    for (int i = tid; i < 2560; i += CNTH) {
        int co = i / 80, r = i % 80;
        dsm[OFF_W2 + (co >> 2) * 320 + r * 4 + (co & 3)] = __ldg(&w2[i]);
    }
    for (int i = tid; i < 2560; i += CNTH) {
        int co = i / 160, r = i % 160;
        dsm[OFF_W3 + (co >> 2) * 640 + r * 4 + (co & 3)] = __ldg(&w3[i]);
    }
    for (int i = tid; i < 160; i += CNTH)  dsm[OFF_W4 + i] = __ldg(&w4[i]);
    if (tid < 16) dsm[OFF_B1 + tid] = __ldg(&b1[tid]);
    if (tid < 32) dsm[OFF_B2 + tid] = __ldg(&b2[tid]);
    if (tid >= 32 && tid < 48) dsm[OFF_B3 + tid - 32] = __ldg(&b3[tid - 32]);
    if (tid >= 48 && tid < 50) dsm[OFF_B4 + tid - 48] = __ldg(&b4[tid - 48]);

    float lower = g_minmax[0], upper = g_minmax[1];
    float dt = (upper - lower) / (float)(TG - 1);

    // ---- psi phase: stage block's candidate window into s2, then gather via LDS ----
    {
        float ls = __ldg(pls), osv = __ldg(pos_);
        float nc2 = -0.5f * LOG2E / (ls * ls);
        float R = fabsf(ls) * RFAC;
        const int nb = b * (NBINS + 1);

        // union of all in-range positions' windows
        int pmin = max(p0, 0), pmax = min(p0 + CW - 1, TG - 1);
        float tmin = lower + pmin * dt, tmax = lower + pmax * dt;
        int blo_all = min(NBINS - 1, max(0, (int)floorf(tmin - R)));
        int bhi_all = min(NBINS - 1, max(0, (int)floorf(tmax + R)));
        int s_all = g_starts[nb + blo_all];
        int e_all = g_starts[nb + bhi_all + 1];
        int sp = (s_all >> 1);                 // first staged PAIR index
        int npair = ((e_all + 1) >> 1) - sp;   // pairs to stage (<= 1024, fits s2)

        // stage pairs (float4 each) into s2
        {
            const float4* src4 = reinterpret_cast<const float4*>(g_sxy + b * NC);
            float4* st4 = reinterpret_cast<float4*>(s2);
            for (int i = tid; i < npair; i += CNTH)
                st4[i] = __ldg(&src4[sp + i]);
        }
        __syncthreads();

        const float4* st4 = reinterpret_cast<const float4*>(s2);
        for (int task = tid; task < CW * 4; task += CNTH) {
            int u = task >> 2, sub = task & 3;
            int p = p0 + u;
            bool in = (p >= 0 && p < TG);
            float t = lower + p * dt;
            float a00 = 0.f, a10 = 0.f, a01 = 0.f, a11 = 0.f;
            if (in) {
                int blo = min(NBINS - 1, max(0, (int)floorf(t - R)));
                int bhi = min(NBINS - 1, max(0, (int)floorf(t + R)));
                int s = g_starts[nb + blo];
                int e = g_starts[nb + bhi + 1];
                int j0 = (s >> 1) - sp + sub;
                int j1 = ((e - 1) >> 1) - sp;
                for (int j = j0; j <= j1; j += 4) {
                    float4 pt = st4[j];
                    float d0 = t - pt.x;
                    float d1 = t - pt.z;
                    float e0 = ex2(d0 * d0 * nc2);
                    float e1 = ex2(d1 * d1 * nc2);
                    a00 += e0; a10 = fmaf(e0, pt.y, a10);
                    a01 += e1; a11 = fmaf(e1, pt.w, a11);
                }
            }
            float a0 = a00 + a01, a1 = a10 + a11;
            #pragma unroll
            for (int off = 2; off; off >>= 1) {
                a0 += __shfl_xor_sync(0xffffffffu, a0, off);
                a1 += __shfl_xor_sync(0xffffffffu, a1, off);
            }
            if (sub == 0) {
                a0 *= osv; a1 *= osv;
                s0[0 * CWP + u] = in ? t : 0.f;
                s0[1 * CWP + u] = a0;
                s0[2 * CWP + u] = in ? a1 / (a0 + EPS) : 0.f;
            }
        }
    }
    __syncthreads();

    conv_layer<16, 3, 2>(s0, s1, reinterpret_cast<const float4*>(dsm + OFF_W1),
                         dsm + OFF_B1, p0, tid);
    __syncthreads();
    conv_layer<32, 16, 4>(s1, s2, reinterpret_cast<const float4*>(dsm + OFF_W2),
                          dsm + OFF_B2, p0, tid);
    __syncthreads();
    conv_layer<16, 32, 6>(s2, s1, reinterpret_cast<const float4*>(dsm + OFF_W3),
                          dsm + OFF_B3, p0, tid);
    __syncthreads();

    if (tid < T_TILE) {
        const float* sw4 = dsm + OFF_W4;
        const float* sb4 = dsm + OFF_B4;
        int u = HALO + tid;
        float acc0 = sb4[0], acc1 = sb4[1];
        #pragma unroll
        for (int ci = 0; ci < 16; ci++) {
            #pragma unroll
            for (int k = 0; k < 5; k++) {
                float xv = s1[ci * CWP + u - 2 + k];
                acc0 = fmaf(sw4[(0 * 16 + ci) * 5 + k], xv, acc0);
                acc1 = fmaf(sw4[(1 * 16 + ci) * 5 + k], xv, acc1);
            }
        }
        int p = p0 + u;
        float sp2 = fmaxf(acc1, 0.f) + log1pf(__expf(-fabsf(acc1)));
        g_f[b * TG + p] = make_float2(acc0, sp2);
    }
}

// ---------------- K3: rho stage — 8 lanes per target, float4 loads ----------------
__global__ void rho_kernel(const float* __restrict__ xt,
                           const float* __restrict__ pls,
                           const float* __restrict__ pos_,
                           float* __restrict__ out) {
    int g = (blockIdx.x * blockDim.x + threadIdx.x) >> 3;
    int sub = threadIdx.x & 7;
    if (g >= BATCH * NT) return;
    int b = g >> 11;

    float lower = g_minmax[0];
    float dt = (g_minmax[1] - lower) / (float)(TG - 1);
    float inv_dt = 1.f / dt;
    float x = __ldg(&xt[g]);
    float ls = __ldg(pls), osv = __ldg(pos_);
    float nc2 = -0.5f * LOG2E / (ls * ls);
    float R = fabsf(ls) * RFAC;

    int ilo = max(0, (int)ceilf((x - R - lower) * inv_dt));
    int ihi = min(TG - 1, (int)floorf((x + R - lower) * inv_dt));

    int j0 = (ilo >> 1) + sub;
    int j1 = ihi >> 1;
    const float4* f4 = reinterpret_cast<const float4*>(g_f + b * TG);
    float mu0 = 0.f, sg0 = 0.f, mu1 = 0.f, sg1 = 0.f;
    float d0 = x - (lower + (float)(2 * j0) * dt);
    float step16 = 16.f * dt;
    for (int j = j0; j <= j1; j += 8) {
        float4 v = __ldg(&f4[j]);
        float d1 = d0 - dt;
        float e0 = ex2(d0 * d0 * nc2);
        float e1 = ex2(d1 * d1 * nc2);
        mu0 = fmaf(e0, v.x, mu0); sg0 = fmaf(e0, v.y, sg0);
        mu1 = fmaf(e1, v.z, mu1); sg1 = fmaf(e1, v.w, sg1);
        d0 -= step16;
    }
    float mu = mu0 + mu1, sg = sg0 + sg1;
    #pragma unroll
    for (int off = 4; off; off >>= 1) {
        mu += __shfl_xor_sync(0xffffffffu, mu, off);
        sg += __shfl_xor_sync(0xffffffffu, sg, off);
    }
    if (sub == 0) {
        reinterpret_cast<float2*>(out)[g] = make_float2(mu * osv, sg * osv);
    }
}

// ---------------- launch ----------------
extern "C" void kernel_launch(void* const* d_in, const int* in_sizes, int n_in,
                              void* d_out, int out_size) {
    const float* xc = (const float*)d_in[0];
    const float* yc = (const float*)d_in[1];
    const float* xt = (const float*)d_in[2];
    const float* ls_psi = (const float*)d_in[3];
    const float* os_psi = (const float*)d_in[4];
    const float* ls_rho = (const float*)d_in[5];
    const float* os_rho = (const float*)d_in[6];
    const float* w1 = (const float*)d_in[7];
    const float* b1 = (const float*)d_in[8];
    const float* w2 = (const float*)d_in[9];
    const float* b2 = (const float*)d_in[10];
    const float* w3 = (const float*)d_in[11];
    const float* b3 = (const float*)d_in[12];
    const float* w4 = (const float*)d_in[13];
    const float* b4 = (const float*)d_in[14];
    float* out = (float*)d_out;

    cudaFuncSetAttribute(cnp_kernel,
                         cudaFuncAttributeMaxDynamicSharedMemorySize, SMEM_BYTES);

    sort_kernel<<<BATCH, SNTH>>>(xc, yc, xt);
    cnp_kernel<<<BATCH * (TG / T_TILE), CNTH, SMEM_BYTES>>>(
        ls_psi, os_psi, w1, b1, w2, b2, w3, b3, w4, b4);
    rho_kernel<<<(BATCH * NT) * 8 / 256, 256>>>(xt, ls_rho, os_rho, out);
}